// round 15
// baseline (speedup 1.0000x reference)
#include <cuda_runtime.h>
#include <cuda_fp16.h>
#include <math.h>
#include <stdint.h>

#define LQ 13294
#define DMODEL 256
#define MAXN 2

// ---------------- scratch (device globals; no allocation) ----------------
__device__ float  g_x[MAXN*LQ*DMODEL];         // [T,256] f32 (residual)
__device__ __half g_x2h[MAXN*LQ*DMODEL];       // [T,256] half
__device__ __half g_fh[MAXN*LQ*DMODEL];        // [T,256] half
__device__ __half g_offattn_h[MAXN*LQ*384];    // [T,384] half
__device__ __half g_value_h[MAXN*LQ*DMODEL];   // [T,256] half (sampling source)
__device__ __half g_src_h[MAXN*LQ*DMODEL];     // half GEMM inputs
__device__ __half g_q_h[MAXN*LQ*DMODEL];
__device__ __half g_samp_h[MAXN*LQ*DMODEL];
__device__ __half g_x_h[MAXN*LQ*DMODEL];
__device__ __half g_h_h[MAXN*LQ*1024];         // FFN intermediate, half only
// transposed half weights [N][K]
__device__ __half g_Wvt[256*256];
__device__ __half g_Wpackt[384*256];
__device__ __half g_Woutt[256*256];
__device__ __half g_W1t[1024*256];
__device__ __half g_W2t[256*1024];
__device__ float  g_bpack[384];

// ---------------- prep: all weight transposes + bias pack in ONE kernel ----------------
__device__ __forceinline__ void do_transpose(const float* in, __half* out, int R, int C,
                                             int bx, int by) {
    __shared__ float tile[32][33];
    int x = bx + threadIdx.x;
    #pragma unroll
    for (int i = 0; i < 4; i++) {
        int y = by + threadIdx.y + i * 8;
        if (y < R && x < C) tile[threadIdx.y + i * 8][threadIdx.x] = in[(size_t)y * C + x];
    }
    __syncthreads();
    int xo = by + threadIdx.x;
    #pragma unroll
    for (int i = 0; i < 4; i++) {
        int yo = bx + threadIdx.y + i * 8;
        if (yo < C && xo < R) out[(size_t)yo * R + xo] = __float2half(tile[threadIdx.x][threadIdx.y + i * 8]);
    }
}

__global__ void prep_w_kernel(const float* __restrict__ Wv, const float* __restrict__ Woff,
                              const float* __restrict__ Wout, const float* __restrict__ Wattn,
                              const float* __restrict__ W1, const float* __restrict__ W2,
                              const float* __restrict__ boff, const float* __restrict__ battn) {
    int id = blockIdx.x;
    if (id < 64)       do_transpose(Wv,   g_Wvt,            256, 256,  (id & 7) * 32,          (id >> 3) * 32);
    else if (id < 128) do_transpose(Woff, g_Wpackt,         256, 256,  ((id - 64) & 7) * 32,   ((id - 64) >> 3) * 32);
    else if (id < 192) do_transpose(Wout, g_Woutt,          256, 256,  ((id - 128) & 7) * 32,  ((id - 128) >> 3) * 32);
    else if (id < 224) do_transpose(Wattn, g_Wpackt + 65536, 256, 128, ((id - 192) & 3) * 32,  ((id - 192) >> 2) * 32);
    else if (id < 480) do_transpose(W1,   g_W1t,            256, 1024, ((id - 224) & 31) * 32, ((id - 224) >> 5) * 32);
    else if (id < 736) do_transpose(W2,   g_W2t,            1024, 256, ((id - 480) & 7) * 32,  ((id - 480) >> 3) * 32);
    else {
        int tid = threadIdx.y * 32 + threadIdx.x;
        if (id == 736) g_bpack[tid] = boff[tid];
        else if (tid < 128) g_bpack[256 + tid] = battn[tid];
    }
}

__global__ void prep_act_kernel(const float* __restrict__ src, const float* __restrict__ pos,
                                int n4) {
    int i = blockIdx.x * blockDim.x + threadIdx.x;
    if (i < n4) {
        float4 vs = ((const float4*)src)[i];
        float4 vp = ((const float4*)pos)[i];
        __half2* os = (__half2*)g_src_h;
        __half2* oq = (__half2*)g_q_h;
        os[2 * i]     = __floats2half2_rn(vs.x, vs.y);
        os[2 * i + 1] = __floats2half2_rn(vs.z, vs.w);
        oq[2 * i]     = __floats2half2_rn(vs.x + vp.x, vs.y + vp.y);
        oq[2 * i + 1] = __floats2half2_rn(vs.z + vp.z, vs.w + vp.w);
    }
}

// ---------------- common PTX helpers ----------------
__device__ __forceinline__ void mma_f16(float* d, const uint32_t* a, const uint32_t* b) {
    asm volatile(
        "mma.sync.aligned.m16n8k16.row.col.f32.f16.f16.f32 "
        "{%0,%1,%2,%3}, {%4,%5,%6,%7}, {%8,%9}, {%0,%1,%2,%3};\n"
        : "+f"(d[0]), "+f"(d[1]), "+f"(d[2]), "+f"(d[3])
        : "r"(a[0]), "r"(a[1]), "r"(a[2]), "r"(a[3]), "r"(b[0]), "r"(b[1]));
}

__device__ __forceinline__ void ldsm_x4(uint32_t& r0, uint32_t& r1, uint32_t& r2, uint32_t& r3,
                                        uint32_t addr) {
    asm volatile("ldmatrix.sync.aligned.m8n8.x4.shared.b16 {%0,%1,%2,%3}, [%4];"
                 : "=r"(r0), "=r"(r1), "=r"(r2), "=r"(r3) : "r"(addr));
}

__device__ __forceinline__ void cp_async16(uint32_t saddr, const void* gptr, int srcbytes) {
    asm volatile("cp.async.cg.shared.global [%0], [%1], 16, %2;\n"
                 :: "r"(saddr), "l"(gptr), "r"(srcbytes));
}
__device__ __forceinline__ void cp_commit() { asm volatile("cp.async.commit_group;\n"); }
template<int N>
__device__ __forceinline__ void cp_wait() { asm volatile("cp.async.wait_group %0;\n" :: "n"(N)); }

// ========= hgemm body: BM128/BN128/BK64, 256 threads (8 warps, 32x64), 3-stage =========
#define BK 64
#define HSTRIDE 72
#define TILE_H (128*HSTRIDE)
#define STAGE_BYTES (2*TILE_H*2)             // 36864 B
#define GEMM_DSMEM (3*STAGE_BYTES)           // 110592 B

template<bool RELU, bool HALF_OUT>
__device__ __forceinline__ void hgemm_body(
    const __half* __restrict__ A, const __half* __restrict__ Bt,
    const float* __restrict__ bias, void* __restrict__ Cv,
    int M, int N, int K, int bm, int bn, char* smem_raw)
{
    const uint32_t smem_u = (uint32_t)__cvta_generic_to_shared(smem_raw);

    const int tid = threadIdx.x;
    const int wid = tid >> 5;
    const int lane = tid & 31;
    const int wm = (wid & 3) * 32;
    const int wn = (wid >> 2) * 64;
    const int r = lane >> 2;
    const int c = lane & 3;

    const int mrow = lane & 7;
    const int mid = lane >> 3;
    const uint32_t a_base0 = smem_u + (uint32_t)(((wm + (mid & 1) * 8 + mrow) * HSTRIDE + (mid >> 1) * 8) * 2);
    const uint32_t a_base1 = a_base0 + 16 * HSTRIDE * 2;
    uint32_t b_base[4];
    #pragma unroll
    for (int q = 0; q < 4; q++)
        b_base[q] = smem_u + TILE_H * 2 +
                    (uint32_t)(((wn + q * 16 + (mid >> 1) * 8 + mrow) * HSTRIDE + (mid & 1) * 8) * 2);

    float acc[2][8][4];
    #pragma unroll
    for (int i = 0; i < 2; i++)
        #pragma unroll
        for (int j = 0; j < 8; j++)
            #pragma unroll
            for (int k = 0; k < 4; k++) acc[i][j][k] = 0.f;

    const int ktiles = K / BK;

    auto issue_tile = [&](int kt, int s) {
        const int kk = kt * BK;
        const uint32_t sb = smem_u + s * STAGE_BYTES;
        #pragma unroll
        for (int i = 0; i < 4; i++) {
            int idx = tid + i * 256;
            int row = idx >> 3, ch = idx & 7;
            int gr = bm + row;
            cp_async16(sb + (row * HSTRIDE + ch * 8) * 2,
                       A + (size_t)gr * K + kk + ch * 8, (gr < M) ? 16 : 0);
        }
        const uint32_t bb = sb + TILE_H * 2;
        #pragma unroll
        for (int i = 0; i < 4; i++) {
            int idx = tid + i * 256;
            int row = idx >> 3, ch = idx & 7;
            cp_async16(bb + (row * HSTRIDE + ch * 8) * 2,
                       Bt + (size_t)(bn + row) * K + kk + ch * 8, 16);
        }
        cp_commit();
    };

    issue_tile(0, 0);
    issue_tile(1, 1);

    for (int kt = 0; kt < ktiles; kt++) {
        const int cur = kt % 3;
        cp_wait<1>();
        __syncthreads();

        if (kt + 2 < ktiles) issue_tile(kt + 2, (kt + 2) % 3);
        else cp_commit();

        const uint32_t sbase = (uint32_t)(cur * STAGE_BYTES);

        #pragma unroll
        for (int ks = 0; ks < 4; ks++) {
            const uint32_t koff = sbase + ks * 32;
            uint32_t af[2][4], bf[8][2];
            ldsm_x4(af[0][0], af[0][1], af[0][2], af[0][3], a_base0 + koff);
            ldsm_x4(af[1][0], af[1][1], af[1][2], af[1][3], a_base1 + koff);
            #pragma unroll
            for (int q = 0; q < 4; q++)
                ldsm_x4(bf[2 * q][0], bf[2 * q][1], bf[2 * q + 1][0], bf[2 * q + 1][1],
                        b_base[q] + koff);
            #pragma unroll
            for (int mt = 0; mt < 2; mt++)
                #pragma unroll
                for (int nt = 0; nt < 8; nt++)
                    mma_f16(acc[mt][nt], af[mt], bf[nt]);
        }
    }

    #pragma unroll
    for (int mt = 0; mt < 2; mt++) {
        #pragma unroll
        for (int nt = 0; nt < 8; nt++) {
            int col = bn + wn + nt * 8 + 2 * c;
            float b0 = __ldg(bias + col), b1 = __ldg(bias + col + 1);
            int row0 = bm + wm + mt * 16 + r;
            int row1 = row0 + 8;
            float v0 = acc[mt][nt][0] + b0, v1 = acc[mt][nt][1] + b1;
            float v2 = acc[mt][nt][2] + b0, v3 = acc[mt][nt][3] + b1;
            if (RELU) {
                v0 = fmaxf(v0, 0.f); v1 = fmaxf(v1, 0.f);
                v2 = fmaxf(v2, 0.f); v3 = fmaxf(v3, 0.f);
            }
            if (HALF_OUT) {
                __half* Ch = (__half*)Cv;
                if (row0 < M) *(__half2*)(Ch + (size_t)row0 * N + col) = __floats2half2_rn(v0, v1);
                if (row1 < M) *(__half2*)(Ch + (size_t)row1 * N + col) = __floats2half2_rn(v2, v3);
            } else {
                float* Cf = (float*)Cv;
                if (row0 < M) *(float2*)(Cf + (size_t)row0 * N + col) = make_float2(v0, v1);
                if (row1 < M) *(float2*)(Cf + (size_t)row1 * N + col) = make_float2(v2, v3);
            }
        }
    }
}

template<bool RELU, bool HALF_OUT>
__global__ void __launch_bounds__(256) hgemm_kernel(
    const __half* __restrict__ A, const __half* __restrict__ Bt,
    const float* __restrict__ bias, void* __restrict__ Cv,
    int M, int N, int K)
{
    extern __shared__ __align__(16) char smem_raw[];
    hgemm_body<RELU, HALF_OUT>(A, Bt, bias, Cv, M, N, K,
                               blockIdx.y * 128, blockIdx.x * 128, smem_raw);
}

// fused GEMM1 (value) + GEMM2 (offattn): z selects; both half-out, K=256
__global__ void __launch_bounds__(256) gemm12_kernel(
    const __half* __restrict__ src_h, const __half* __restrict__ Wvt,
    const float* __restrict__ bv, __half* __restrict__ value_h,
    const __half* __restrict__ q_h, const __half* __restrict__ Wpackt,
    const float* __restrict__ bpack, __half* __restrict__ offattn_h,
    int M)
{
    extern __shared__ __align__(16) char smem_raw[];
    if (blockIdx.z == 0) {
        if (blockIdx.x >= 2) return;
        hgemm_body<false, true>(src_h, Wvt, bv, value_h, M, 256, 256,
                                blockIdx.y * 128, blockIdx.x * 128, smem_raw);
    } else {
        hgemm_body<false, true>(q_h, Wpackt, bpack, offattn_h, M, 384, 256,
                                blockIdx.y * 128, blockIdx.x * 128, smem_raw);
    }
}

// ---------------- deformable sampling: 4 heads/warp, 4 tokens/block, MLP-8 gathers ----------------
// 256 threads = 4 tokens x 2 warps. Lane = (hs = lane>>3, q = lane&7); head = w*4+hs.
__global__ void __launch_bounds__(256) sample_kernel(const float* __restrict__ rp, int T)
{
    const int lane = threadIdx.x & 31;
    const unsigned FULL = 0xffffffffu;

    const int t = blockIdx.x * 4 + (threadIdx.x >> 6);
    if (t >= T) return;
    const int w = (threadIdx.x >> 5) & 1;
    const int hs = lane >> 3;
    const int q = lane & 7;
    const int h = w * 4 + hs;

    const __half* raw = g_offattn_h + (size_t)t * 384;

    float2 offA = __half22float2(*(const __half2*)(raw + h * 32 + q * 2));
    float2 offB = __half22float2(*(const __half2*)(raw + h * 32 + (q + 8) * 2));
    float lA = __half2float(raw[256 + h * 16 + q]);
    float lB = __half2float(raw[256 + h * 16 + q + 8]);

    // softmax over 16 points of head h (8-lane group, 2 logits per lane)
    float m = fmaxf(lA, lB);
    #pragma unroll
    for (int o = 4; o; o >>= 1) m = fmaxf(m, __shfl_xor_sync(FULL, m, o));
    float eA = __expf(lA - m), eB = __expf(lB - m);
    float s = eA + eB;
    #pragma unroll
    for (int o = 4; o; o >>= 1) s += __shfl_xor_sync(FULL, s, o);
    const float aA = eA / s, aB = eB / s;

    const int LSa[4] = {0, 10000, 12500, 13125};
    const int Wla[4] = {100, 50, 25, 13};

    int   idxA[4], idxB[4];
    float wsA[4], wsB[4];
    #pragma unroll
    for (int half_sel = 0; half_sel < 2; half_sel++) {
        const int p = half_sel ? (q + 8) : q;
        const float2 off = half_sel ? offB : offA;
        const float an = half_sel ? aB : aA;
        const int l = p >> 2;
        const int Wi = Wla[l];
        const float rx = __ldg(rp + (size_t)t * 8 + 2 * l);
        const float ry = __ldg(rp + (size_t)t * 8 + 2 * l + 1);
        float x = rx * (float)Wi + off.x - 0.5f;
        float y = ry * (float)Wi + off.y - 0.5f;
        float xf = floorf(x), yf = floorf(y);
        int x0 = (int)xf, y0 = (int)yf;
        float wx1 = x - xf, wy1 = y - yf;
        float wx0 = 1.f - wx1, wy0 = 1.f - wy1;
        #pragma unroll
        for (int tap = 0; tap < 4; tap++) {
            int dx = tap & 1, dy = tap >> 1;
            int xi = x0 + dx, yi = y0 + dy;
            bool valid = (xi >= 0) & (xi < Wi) & (yi >= 0) & (yi < Wi);
            float ww = (dx ? wx1 : wx0) * (dy ? wy1 : wy0) * an;
            int xic = min(max(xi, 0), Wi - 1);
            int yic = min(max(yi, 0), Wi - 1);
            int ii = LSa[l] + yic * Wi + xic;
            if (half_sel) { idxB[tap] = ii; wsB[tap] = valid ? ww : 0.f; }
            else          { idxA[tap] = ii; wsA[tap] = valid ? ww : 0.f; }
        }
    }

    // gather: lane covers channels q*4 .. q*4+3 of head h; A/B halves interleaved (MLP 8)
    const int n = (t >= LQ) ? 1 : 0;
    const uint2* vb = (const uint2*)(g_value_h + ((size_t)n * LQ) * 256 + h * 32 + q * 4);

    float ac[4][4];
    #pragma unroll
    for (int i = 0; i < 4; i++)
        #pragma unroll
        for (int j = 0; j < 4; j++) ac[i][j] = 0.f;

    const int gbase = lane & 24;
    #pragma unroll
    for (int pi = 0; pi < 8; pi++) {
        const int sl = gbase | pi;
        int iA[4], iB[4];
        float wA[4], wB[4];
        #pragma unroll
        for (int tap = 0; tap < 4; tap++) {
            iA[tap] = __shfl_sync(FULL, idxA[tap], sl);
            wA[tap] = __shfl_sync(FULL, wsA[tap], sl);
            iB[tap] = __shfl_sync(FULL, idxB[tap], sl);
            wB[tap] = __shfl_sync(FULL, wsB[tap], sl);
        }
        uint2 rA[4], rB[4];
        #pragma unroll
        for (int tap = 0; tap < 4; tap++) rA[tap] = __ldg(vb + (size_t)iA[tap] * 64);
        #pragma unroll
        for (int tap = 0; tap < 4; tap++) rB[tap] = __ldg(vb + (size_t)iB[tap] * 64);
        #pragma unroll
        for (int tap = 0; tap < 4; tap++) {
            float2 lo = __half22float2(*(const __half2*)&rA[tap].x);
            float2 hi = __half22float2(*(const __half2*)&rA[tap].y);
            ac[tap][0] = fmaf(wA[tap], lo.x, ac[tap][0]);
            ac[tap][1] = fmaf(wA[tap], lo.y, ac[tap][1]);
            ac[tap][2] = fmaf(wA[tap], hi.x, ac[tap][2]);
            ac[tap][3] = fmaf(wA[tap], hi.y, ac[tap][3]);
        }
        #pragma unroll
        for (int tap = 0; tap < 4; tap++) {
            float2 lo = __half22float2(*(const __half2*)&rB[tap].x);
            float2 hi = __half22float2(*(const __half2*)&rB[tap].y);
            ac[tap][0] = fmaf(wB[tap], lo.x, ac[tap][0]);
            ac[tap][1] = fmaf(wB[tap], lo.y, ac[tap][1]);
            ac[tap][2] = fmaf(wB[tap], hi.x, ac[tap][2]);
            ac[tap][3] = fmaf(wB[tap], hi.y, ac[tap][3]);
        }
    }

    float o0 = (ac[0][0] + ac[1][0]) + (ac[2][0] + ac[3][0]);
    float o1 = (ac[0][1] + ac[1][1]) + (ac[2][1] + ac[3][1]);
    float o2 = (ac[0][2] + ac[1][2]) + (ac[2][2] + ac[3][2]);
    float o3 = (ac[0][3] + ac[1][3]) + (ac[2][3] + ac[3][3]);

    __half2 h01 = __floats2half2_rn(o0, o1);
    __half2 h23 = __floats2half2_rn(o2, o3);
    uint2 outv;
    outv.x = *(uint32_t*)&h01;
    outv.y = *(uint32_t*)&h23;
    *(uint2*)(g_samp_h + (size_t)t * 256 + h * 32 + q * 4) = outv;
}

// ---------------- LayerNorm: warp/token; a f32 + b half; out = LN(a+b)*g + be ----------------
template<bool WRITEH>
__global__ void __launch_bounds__(256) ln_kernel(
    const float* __restrict__ a, const __half* __restrict__ b,
    const float* __restrict__ g, const float* __restrict__ be,
    float* __restrict__ out, __half* __restrict__ outh, int T)
{
    const int warp = (blockIdx.x * blockDim.x + threadIdx.x) >> 5;
    if (warp >= T) return;
    const int lane = threadIdx.x & 31;
    const size_t base = (size_t)warp * 256 + lane * 8;

    float4 a0 = *(const float4*)(a + base);
    float4 a1 = *(const float4*)(a + base + 4);
    uint4 braw = *(const uint4*)(b + base);   // 8 halves
    float2 b0 = __half22float2(*(const __half2*)&braw.x);
    float2 b1 = __half22float2(*(const __half2*)&braw.y);
    float2 b2 = __half22float2(*(const __half2*)&braw.z);
    float2 b3 = __half22float2(*(const __half2*)&braw.w);
    float v[8] = {a0.x + b0.x, a0.y + b0.y, a0.z + b1.x, a0.w + b1.y,
                  a1.x + b2.x, a1.y + b2.y, a1.z + b3.x, a1.w + b3.y};
    float s = 0.f, s2 = 0.f;
    #pragma unroll
    for (int i = 0; i < 8; i++) { s += v[i]; s2 = fmaf(v[i], v[i], s2); }
    #pragma unroll
    for (int o = 16; o; o >>= 1) {
        s  += __shfl_xor_sync(0xffffffffu, s,  o);
        s2 += __shfl_xor_sync(0xffffffffu, s2, o);
    }
    float mu = s * (1.f / 256.f);
    float var = s2 * (1.f / 256.f) - mu * mu;
    float rstd = rsqrtf(var + 1e-5f);

    float4 gg0 = *(const float4*)(g + lane * 8);
    float4 gg1 = *(const float4*)(g + lane * 8 + 4);
    float4 bb0 = *(const float4*)(be + lane * 8);
    float4 bb1 = *(const float4*)(be + lane * 8 + 4);
    float gv[8] = {gg0.x, gg0.y, gg0.z, gg0.w, gg1.x, gg1.y, gg1.z, gg1.w};
    float bv[8] = {bb0.x, bb0.y, bb0.z, bb0.w, bb1.x, bb1.y, bb1.z, bb1.w};
    float o0[8];
    #pragma unroll
    for (int i = 0; i < 8; i++) o0[i] = (v[i] - mu) * rstd * gv[i] + bv[i];
    *(float4*)(out + base)     = make_float4(o0[0], o0[1], o0[2], o0[3]);
    *(float4*)(out + base + 4) = make_float4(o0[4], o0[5], o0[6], o0[7]);
    if (WRITEH) {
        __half2* oh = (__half2*)(outh + base);
        oh[0] = __floats2half2_rn(o0[0], o0[1]);
        oh[1] = __floats2half2_rn(o0[2], o0[3]);
        oh[2] = __floats2half2_rn(o0[4], o0[5]);
        oh[3] = __floats2half2_rn(o0[6], o0[7]);
    }
}

// ---------------- host launcher ----------------
extern "C" void kernel_launch(void* const* d_in, const int* in_sizes, int n_in,
                              void* d_out, int out_size)
{
    const float* src   = (const float*)d_in[0];
    const float* pos   = (const float*)d_in[1];
    const float* rp    = (const float*)d_in[2];
    const float* Wv    = (const float*)d_in[5];
    const float* bv    = (const float*)d_in[6];
    const float* Woff  = (const float*)d_in[7];
    const float* boff  = (const float*)d_in[8];
    const float* Wattn = (const float*)d_in[9];
    const float* battn = (const float*)d_in[10];
    const float* Wout  = (const float*)d_in[11];
    const float* bout  = (const float*)d_in[12];
    const float* W1    = (const float*)d_in[13];
    const float* b1    = (const float*)d_in[14];
    const float* W2    = (const float*)d_in[15];
    const float* b2    = (const float*)d_in[16];
    const float* g1    = (const float*)d_in[17];
    const float* be1   = (const float*)d_in[18];
    const float* g2    = (const float*)d_in[19];
    const float* be2   = (const float*)d_in[20];

    const int T = in_sizes[0] / DMODEL;   // N * Lq

    float  *p_x, *p_bpack;
    __half *p_x2h, *p_fh, *p_offattn_h, *p_value_h, *p_src_h, *p_q_h, *p_samp_h, *p_x_h, *p_h_h;
    __half *p_Wvt, *p_Wpackt, *p_Woutt, *p_W1t, *p_W2t;
    cudaGetSymbolAddress((void**)&p_x,       g_x);
    cudaGetSymbolAddress((void**)&p_x2h,     g_x2h);
    cudaGetSymbolAddress((void**)&p_fh,      g_fh);
    cudaGetSymbolAddress((void**)&p_bpack,   g_bpack);
    cudaGetSymbolAddress((void**)&p_offattn_h, g_offattn_h);
    cudaGetSymbolAddress((void**)&p_value_h, g_value_h);
    cudaGetSymbolAddress((void**)&p_src_h,   g_src_h);
    cudaGetSymbolAddress((void**)&p_q_h,     g_q_h);
    cudaGetSymbolAddress((void**)&p_samp_h,  g_samp_h);
    cudaGetSymbolAddress((void**)&p_x_h,     g_x_h);
    cudaGetSymbolAddress((void**)&p_h_h,     g_h_h);
    cudaGetSymbolAddress((void**)&p_Wvt,     g_Wvt);
    cudaGetSymbolAddress((void**)&p_Wpackt,  g_Wpackt);
    cudaGetSymbolAddress((void**)&p_Woutt,   g_Woutt);
    cudaGetSymbolAddress((void**)&p_W1t,     g_W1t);
    cudaGetSymbolAddress((void**)&p_W2t,     g_W2t);

    cudaFuncSetAttribute(hgemm_kernel<false, true>, cudaFuncAttributeMaxDynamicSharedMemorySize, GEMM_DSMEM);
    cudaFuncSetAttribute(hgemm_kernel<true,  true>, cudaFuncAttributeMaxDynamicSharedMemorySize, GEMM_DSMEM);
    cudaFuncSetAttribute(gemm12_kernel, cudaFuncAttributeMaxDynamicSharedMemorySize, GEMM_DSMEM);

    const int MB = (T + 127) / 128;
    const int n4 = T * DMODEL / 4;
    dim3 tb(32, 8);

    // ---- prep (2 launches) ----
    prep_w_kernel<<<738, tb>>>(Wv, Woff, Wout, Wattn, W1, W2, boff, battn);
    prep_act_kernel<<<(n4 + 255) / 256, 256>>>(src, pos, n4);

    // 1+2. value = src @ Wv + bv (half) ; offattn = q @ [W_off|W_attn] + b (half)
    gemm12_kernel<<<dim3(3, MB, 2), 256, GEMM_DSMEM>>>(
        p_src_h, p_Wvt, bv, p_value_h, p_q_h, p_Wpackt, p_bpack, p_offattn_h, T);

    // 3. deformable sampling + softmax fused (half out)
    sample_kernel<<<(T + 3) / 4, 256>>>(rp, T);

    // 4. x2 = samp @ W_out + b_out        (half out)
    hgemm_kernel<false, true><<<dim3(2, MB), 256, GEMM_DSMEM>>>(p_samp_h, p_Woutt, bout, p_x2h, T, 256, 256);

    // 5. x = LN(src + x2)                 (f32 + half)
    ln_kernel<true><<<(T * 32 + 255) / 256, 256>>>(src, p_x2h, g1, be1, p_x, p_x_h, T);

    // 6. h = relu(x @ W1 + b1)            (half out only)
    hgemm_kernel<true, true><<<dim3(8, MB), 256, GEMM_DSMEM>>>(p_x_h, p_W1t, b1, p_h_h, T, 1024, 256);

    // 7. f = h @ W2 + b2                  (half out)
    hgemm_kernel<false, true><<<dim3(2, MB), 256, GEMM_DSMEM>>>(p_h_h, p_W2t, b2, p_fh, T, 256, 1024);

    // 8. out = LN(x + f)
    ln_kernel<false><<<(T * 32 + 255) / 256, 256>>>(p_x, p_fh, g2, be2, (float*)d_out, nullptr, T);
}

// round 16
// speedup vs baseline: 1.0670x; 1.0670x over previous
#include <cuda_runtime.h>
#include <cuda_fp16.h>
#include <math.h>
#include <stdint.h>

#define LQ 13294
#define DMODEL 256
#define MAXN 2

// ---------------- scratch (device globals; no allocation) ----------------
__device__ float  g_x[MAXN*LQ*DMODEL];         // [T,256] f32 (residual)
__device__ __half g_x2h[MAXN*LQ*DMODEL];       // [T,256] half
__device__ __half g_fh[MAXN*LQ*DMODEL];        // [T,256] half
__device__ __half g_offattn_h[MAXN*LQ*384];    // [T,384] half
__device__ __half g_value_h[MAXN*LQ*DMODEL];   // [T,256] half (sampling source)
__device__ __half g_src_h[MAXN*LQ*DMODEL];     // half GEMM inputs
__device__ __half g_q_h[MAXN*LQ*DMODEL];
__device__ __half g_samp_h[MAXN*LQ*DMODEL];
__device__ __half g_x_h[MAXN*LQ*DMODEL];
__device__ __half g_h_h[MAXN*LQ*1024];         // FFN intermediate, half only
// transposed half weights [N][K]
__device__ __half g_Wvt[256*256];
__device__ __half g_Wpackt[384*256];
__device__ __half g_Woutt[256*256];
__device__ __half g_W1t[1024*256];
__device__ __half g_W2t[256*1024];
__device__ float  g_bpack[384];

// ---------------- prep: all weight transposes + bias pack in ONE kernel ----------------
__device__ __forceinline__ void do_transpose(const float* in, __half* out, int R, int C,
                                             int bx, int by) {
    __shared__ float tile[32][33];
    int x = bx + threadIdx.x;
    #pragma unroll
    for (int i = 0; i < 4; i++) {
        int y = by + threadIdx.y + i * 8;
        if (y < R && x < C) tile[threadIdx.y + i * 8][threadIdx.x] = in[(size_t)y * C + x];
    }
    __syncthreads();
    int xo = by + threadIdx.x;
    #pragma unroll
    for (int i = 0; i < 4; i++) {
        int yo = bx + threadIdx.y + i * 8;
        if (yo < C && xo < R) out[(size_t)yo * R + xo] = __float2half(tile[threadIdx.x][threadIdx.y + i * 8]);
    }
}

__global__ void prep_w_kernel(const float* __restrict__ Wv, const float* __restrict__ Woff,
                              const float* __restrict__ Wout, const float* __restrict__ Wattn,
                              const float* __restrict__ W1, const float* __restrict__ W2,
                              const float* __restrict__ boff, const float* __restrict__ battn) {
    int id = blockIdx.x;
    if (id < 64)       do_transpose(Wv,   g_Wvt,            256, 256,  (id & 7) * 32,          (id >> 3) * 32);
    else if (id < 128) do_transpose(Woff, g_Wpackt,         256, 256,  ((id - 64) & 7) * 32,   ((id - 64) >> 3) * 32);
    else if (id < 192) do_transpose(Wout, g_Woutt,          256, 256,  ((id - 128) & 7) * 32,  ((id - 128) >> 3) * 32);
    else if (id < 224) do_transpose(Wattn, g_Wpackt + 65536, 256, 128, ((id - 192) & 3) * 32,  ((id - 192) >> 2) * 32);
    else if (id < 480) do_transpose(W1,   g_W1t,            256, 1024, ((id - 224) & 31) * 32, ((id - 224) >> 5) * 32);
    else if (id < 736) do_transpose(W2,   g_W2t,            1024, 256, ((id - 480) & 7) * 32,  ((id - 480) >> 3) * 32);
    else {
        int tid = threadIdx.y * 32 + threadIdx.x;
        if (id == 736) g_bpack[tid] = boff[tid];
        else if (tid < 128) g_bpack[256 + tid] = battn[tid];
    }
}

__global__ void prep_act_kernel(const float* __restrict__ src, const float* __restrict__ pos,
                                int n4) {
    int i = blockIdx.x * blockDim.x + threadIdx.x;
    if (i < n4) {
        float4 vs = ((const float4*)src)[i];
        float4 vp = ((const float4*)pos)[i];
        __half2* os = (__half2*)g_src_h;
        __half2* oq = (__half2*)g_q_h;
        os[2 * i]     = __floats2half2_rn(vs.x, vs.y);
        os[2 * i + 1] = __floats2half2_rn(vs.z, vs.w);
        oq[2 * i]     = __floats2half2_rn(vs.x + vp.x, vs.y + vp.y);
        oq[2 * i + 1] = __floats2half2_rn(vs.z + vp.z, vs.w + vp.w);
    }
}

// ---------------- common PTX helpers ----------------
__device__ __forceinline__ void mma_f16(float* d, const uint32_t* a, const uint32_t* b) {
    asm volatile(
        "mma.sync.aligned.m16n8k16.row.col.f32.f16.f16.f32 "
        "{%0,%1,%2,%3}, {%4,%5,%6,%7}, {%8,%9}, {%0,%1,%2,%3};\n"
        : "+f"(d[0]), "+f"(d[1]), "+f"(d[2]), "+f"(d[3])
        : "r"(a[0]), "r"(a[1]), "r"(a[2]), "r"(a[3]), "r"(b[0]), "r"(b[1]));
}

__device__ __forceinline__ void ldsm_x4(uint32_t& r0, uint32_t& r1, uint32_t& r2, uint32_t& r3,
                                        uint32_t addr) {
    asm volatile("ldmatrix.sync.aligned.m8n8.x4.shared.b16 {%0,%1,%2,%3}, [%4];"
                 : "=r"(r0), "=r"(r1), "=r"(r2), "=r"(r3) : "r"(addr));
}

__device__ __forceinline__ void cp_async16(uint32_t saddr, const void* gptr, int srcbytes) {
    asm volatile("cp.async.cg.shared.global [%0], [%1], 16, %2;\n"
                 :: "r"(saddr), "l"(gptr), "r"(srcbytes));
}
__device__ __forceinline__ void cp_commit() { asm volatile("cp.async.commit_group;\n"); }
template<int N>
__device__ __forceinline__ void cp_wait() { asm volatile("cp.async.wait_group %0;\n" :: "n"(N)); }

// ========= hgemm body: BM128/BN128/BK64, 256 threads (8 warps, 32x64), 3-stage =========
#define BK 64
#define HSTRIDE 72
#define TILE_H (128*HSTRIDE)
#define STAGE_BYTES (2*TILE_H*2)             // 36864 B
#define GEMM_DSMEM (3*STAGE_BYTES)           // 110592 B

template<bool RELU, bool HALF_OUT>
__device__ __forceinline__ void hgemm_body(
    const __half* __restrict__ A, const __half* __restrict__ Bt,
    const float* __restrict__ bias, void* __restrict__ Cv,
    int M, int N, int K, int bm, int bn, char* smem_raw)
{
    const uint32_t smem_u = (uint32_t)__cvta_generic_to_shared(smem_raw);

    const int tid = threadIdx.x;
    const int wid = tid >> 5;
    const int lane = tid & 31;
    const int wm = (wid & 3) * 32;
    const int wn = (wid >> 2) * 64;
    const int r = lane >> 2;
    const int c = lane & 3;

    const int mrow = lane & 7;
    const int mid = lane >> 3;
    const uint32_t a_base0 = smem_u + (uint32_t)(((wm + (mid & 1) * 8 + mrow) * HSTRIDE + (mid >> 1) * 8) * 2);
    const uint32_t a_base1 = a_base0 + 16 * HSTRIDE * 2;
    uint32_t b_base[4];
    #pragma unroll
    for (int q = 0; q < 4; q++)
        b_base[q] = smem_u + TILE_H * 2 +
                    (uint32_t)(((wn + q * 16 + (mid >> 1) * 8 + mrow) * HSTRIDE + (mid & 1) * 8) * 2);

    float acc[2][8][4];
    #pragma unroll
    for (int i = 0; i < 2; i++)
        #pragma unroll
        for (int j = 0; j < 8; j++)
            #pragma unroll
            for (int k = 0; k < 4; k++) acc[i][j][k] = 0.f;

    const int ktiles = K / BK;

    auto issue_tile = [&](int kt, int s) {
        const int kk = kt * BK;
        const uint32_t sb = smem_u + s * STAGE_BYTES;
        #pragma unroll
        for (int i = 0; i < 4; i++) {
            int idx = tid + i * 256;
            int row = idx >> 3, ch = idx & 7;
            int gr = bm + row;
            cp_async16(sb + (row * HSTRIDE + ch * 8) * 2,
                       A + (size_t)gr * K + kk + ch * 8, (gr < M) ? 16 : 0);
        }
        const uint32_t bb = sb + TILE_H * 2;
        #pragma unroll
        for (int i = 0; i < 4; i++) {
            int idx = tid + i * 256;
            int row = idx >> 3, ch = idx & 7;
            cp_async16(bb + (row * HSTRIDE + ch * 8) * 2,
                       Bt + (size_t)(bn + row) * K + kk + ch * 8, 16);
        }
        cp_commit();
    };

    issue_tile(0, 0);
    issue_tile(1, 1);

    for (int kt = 0; kt < ktiles; kt++) {
        const int cur = kt % 3;
        cp_wait<1>();
        __syncthreads();

        if (kt + 2 < ktiles) issue_tile(kt + 2, (kt + 2) % 3);
        else cp_commit();

        const uint32_t sbase = (uint32_t)(cur * STAGE_BYTES);

        #pragma unroll
        for (int ks = 0; ks < 4; ks++) {
            const uint32_t koff = sbase + ks * 32;
            uint32_t af[2][4], bf[8][2];
            ldsm_x4(af[0][0], af[0][1], af[0][2], af[0][3], a_base0 + koff);
            ldsm_x4(af[1][0], af[1][1], af[1][2], af[1][3], a_base1 + koff);
            #pragma unroll
            for (int q = 0; q < 4; q++)
                ldsm_x4(bf[2 * q][0], bf[2 * q][1], bf[2 * q + 1][0], bf[2 * q + 1][1],
                        b_base[q] + koff);
            #pragma unroll
            for (int mt = 0; mt < 2; mt++)
                #pragma unroll
                for (int nt = 0; nt < 8; nt++)
                    mma_f16(acc[mt][nt], af[mt], bf[nt]);
        }
    }

    #pragma unroll
    for (int mt = 0; mt < 2; mt++) {
        #pragma unroll
        for (int nt = 0; nt < 8; nt++) {
            int col = bn + wn + nt * 8 + 2 * c;
            float b0 = __ldg(bias + col), b1 = __ldg(bias + col + 1);
            int row0 = bm + wm + mt * 16 + r;
            int row1 = row0 + 8;
            float v0 = acc[mt][nt][0] + b0, v1 = acc[mt][nt][1] + b1;
            float v2 = acc[mt][nt][2] + b0, v3 = acc[mt][nt][3] + b1;
            if (RELU) {
                v0 = fmaxf(v0, 0.f); v1 = fmaxf(v1, 0.f);
                v2 = fmaxf(v2, 0.f); v3 = fmaxf(v3, 0.f);
            }
            if (HALF_OUT) {
                __half* Ch = (__half*)Cv;
                if (row0 < M) *(__half2*)(Ch + (size_t)row0 * N + col) = __floats2half2_rn(v0, v1);
                if (row1 < M) *(__half2*)(Ch + (size_t)row1 * N + col) = __floats2half2_rn(v2, v3);
            } else {
                float* Cf = (float*)Cv;
                if (row0 < M) *(float2*)(Cf + (size_t)row0 * N + col) = make_float2(v0, v1);
                if (row1 < M) *(float2*)(Cf + (size_t)row1 * N + col) = make_float2(v2, v3);
            }
        }
    }
}

template<bool RELU, bool HALF_OUT>
__global__ void __launch_bounds__(256) hgemm_kernel(
    const __half* __restrict__ A, const __half* __restrict__ Bt,
    const float* __restrict__ bias, void* __restrict__ Cv,
    int M, int N, int K)
{
    extern __shared__ __align__(16) char smem_raw[];
    hgemm_body<RELU, HALF_OUT>(A, Bt, bias, Cv, M, N, K,
                               blockIdx.y * 128, blockIdx.x * 128, smem_raw);
}

// fused GEMM1 (value) + GEMM2 (offattn): z selects; both half-out, K=256
__global__ void __launch_bounds__(256) gemm12_kernel(
    const __half* __restrict__ src_h, const __half* __restrict__ Wvt,
    const float* __restrict__ bv, __half* __restrict__ value_h,
    const __half* __restrict__ q_h, const __half* __restrict__ Wpackt,
    const float* __restrict__ bpack, __half* __restrict__ offattn_h,
    int M)
{
    extern __shared__ __align__(16) char smem_raw[];
    if (blockIdx.z == 0) {
        if (blockIdx.x >= 2) return;
        hgemm_body<false, true>(src_h, Wvt, bv, value_h, M, 256, 256,
                                blockIdx.y * 128, blockIdx.x * 128, smem_raw);
    } else {
        hgemm_body<false, true>(q_h, Wpackt, bpack, offattn_h, M, 384, 256,
                                blockIdx.y * 128, blockIdx.x * 128, smem_raw);
    }
}

// ---------------- deformable sampling: 4 heads per warp, half2 FMA gathers ----------------
// 128 threads = 2 tokens x 2 warps. Lane = (hs = lane>>3, q = lane&7); head = w*4+hs.
// Lane precomputes taps/weights (packed half2) for points q and q+8; gathers cover
// channels q*4..q*4+3; accumulation in half2 (per-tap accumulators, fp32 final sum).
__global__ void __launch_bounds__(128) sample_kernel(const float* __restrict__ rp, int T)
{
    const int widx = threadIdx.x >> 5;
    const int lane = threadIdx.x & 31;
    const unsigned FULL = 0xffffffffu;

    const int t = blockIdx.x * 2 + (widx >> 1);
    if (t >= T) return;
    const int w = widx & 1;
    const int hs = lane >> 3;
    const int q = lane & 7;
    const int h = w * 4 + hs;

    const __half* raw = g_offattn_h + (size_t)t * 384;

    float2 offA = __half22float2(*(const __half2*)(raw + h * 32 + q * 2));
    float2 offB = __half22float2(*(const __half2*)(raw + h * 32 + (q + 8) * 2));
    float lA = __half2float(raw[256 + h * 16 + q]);
    float lB = __half2float(raw[256 + h * 16 + q + 8]);

    // softmax over 16 points of head h (8-lane group, 2 logits per lane)
    float m = fmaxf(lA, lB);
    #pragma unroll
    for (int o = 4; o; o >>= 1) m = fmaxf(m, __shfl_xor_sync(FULL, m, o));
    float eA = __expf(lA - m), eB = __expf(lB - m);
    float s = eA + eB;
    #pragma unroll
    for (int o = 4; o; o >>= 1) s += __shfl_xor_sync(FULL, s, o);
    const float aA = eA / s, aB = eB / s;

    const int LSa[4] = {0, 10000, 12500, 13125};
    const int Wla[4] = {100, 50, 25, 13};

    int      idxA[4], idxB[4];
    uint32_t wsA[4], wsB[4];       // half2(w, w) bit patterns
    #pragma unroll
    for (int half_sel = 0; half_sel < 2; half_sel++) {
        const int p = half_sel ? (q + 8) : q;
        const float2 off = half_sel ? offB : offA;
        const float an = half_sel ? aB : aA;
        const int l = p >> 2;
        const int Wi = Wla[l];
        const float rx = __ldg(rp + (size_t)t * 8 + 2 * l);
        const float ry = __ldg(rp + (size_t)t * 8 + 2 * l + 1);
        float x = rx * (float)Wi + off.x - 0.5f;
        float y = ry * (float)Wi + off.y - 0.5f;
        float xf = floorf(x), yf = floorf(y);
        int x0 = (int)xf, y0 = (int)yf;
        float wx1 = x - xf, wy1 = y - yf;
        float wx0 = 1.f - wx1, wy0 = 1.f - wy1;
        #pragma unroll
        for (int tap = 0; tap < 4; tap++) {
            int dx = tap & 1, dy = tap >> 1;
            int xi = x0 + dx, yi = y0 + dy;
            bool valid = (xi >= 0) & (xi < Wi) & (yi >= 0) & (yi < Wi);
            float ww = (dx ? wx1 : wx0) * (dy ? wy1 : wy0) * an;
            ww = valid ? ww : 0.f;
            int xic = min(max(xi, 0), Wi - 1);
            int yic = min(max(yi, 0), Wi - 1);
            int ii = LSa[l] + yic * Wi + xic;
            __half2 w2 = __float2half2_rn(ww);
            uint32_t wu = *(uint32_t*)&w2;
            if (half_sel) { idxB[tap] = ii; wsB[tap] = wu; }
            else          { idxA[tap] = ii; wsA[tap] = wu; }
        }
    }

    // gather: lane covers channels q*4 .. q*4+3 of head h
    const int n = (t >= LQ) ? 1 : 0;
    const uint2* vb = (const uint2*)(g_value_h + ((size_t)n * LQ) * 256 + h * 32 + q * 4);

    __half2 ac01[4], ac23[4];
    #pragma unroll
    for (int i = 0; i < 4; i++) {
        ac01[i] = __floats2half2_rn(0.f, 0.f);
        ac23[i] = __floats2half2_rn(0.f, 0.f);
    }

    const int gbase = lane & 24;
    #pragma unroll
    for (int pi = 0; pi < 8; pi++) {
        const int sl = gbase | pi;
        #pragma unroll
        for (int tap = 0; tap < 4; tap++) {
            int ii = __shfl_sync(FULL, idxA[tap], sl);
            uint32_t wu = __shfl_sync(FULL, wsA[tap], sl);
            __half2 w2 = *(__half2*)&wu;
            uint2 rv = __ldg(vb + (size_t)ii * 64);
            ac01[tap] = __hfma2(w2, *(const __half2*)&rv.x, ac01[tap]);
            ac23[tap] = __hfma2(w2, *(const __half2*)&rv.y, ac23[tap]);
        }
    }
    #pragma unroll
    for (int pi = 0; pi < 8; pi++) {
        const int sl = gbase | pi;
        #pragma unroll
        for (int tap = 0; tap < 4; tap++) {
            int ii = __shfl_sync(FULL, idxB[tap], sl);
            uint32_t wu = __shfl_sync(FULL, wsB[tap], sl);
            __half2 w2 = *(__half2*)&wu;
            uint2 rv = __ldg(vb + (size_t)ii * 64);
            ac01[tap] = __hfma2(w2, *(const __half2*)&rv.x, ac01[tap]);
            ac23[tap] = __hfma2(w2, *(const __half2*)&rv.y, ac23[tap]);
        }
    }

    // final cross-tap reduction in fp32
    float2 f01[4], f23[4];
    #pragma unroll
    for (int i = 0; i < 4; i++) { f01[i] = __half22float2(ac01[i]); f23[i] = __half22float2(ac23[i]); }
    float o0 = (f01[0].x + f01[1].x) + (f01[2].x + f01[3].x);
    float o1 = (f01[0].y + f01[1].y) + (f01[2].y + f01[3].y);
    float o2 = (f23[0].x + f23[1].x) + (f23[2].x + f23[3].x);
    float o3 = (f23[0].y + f23[1].y) + (f23[2].y + f23[3].y);

    __half2 h01 = __floats2half2_rn(o0, o1);
    __half2 h23 = __floats2half2_rn(o2, o3);
    uint2 outv;
    outv.x = *(uint32_t*)&h01;
    outv.y = *(uint32_t*)&h23;
    *(uint2*)(g_samp_h + (size_t)t * 256 + h * 32 + q * 4) = outv;
}

// ---------------- LayerNorm: warp/token; a f32 + b half; out = LN(a+b)*g + be ----------------
template<bool WRITEH>
__global__ void __launch_bounds__(256) ln_kernel(
    const float* __restrict__ a, const __half* __restrict__ b,
    const float* __restrict__ g, const float* __restrict__ be,
    float* __restrict__ out, __half* __restrict__ outh, int T)
{
    const int warp = (blockIdx.x * blockDim.x + threadIdx.x) >> 5;
    if (warp >= T) return;
    const int lane = threadIdx.x & 31;
    const size_t base = (size_t)warp * 256 + lane * 8;

    float4 a0 = *(const float4*)(a + base);
    float4 a1 = *(const float4*)(a + base + 4);
    uint4 braw = *(const uint4*)(b + base);   // 8 halves
    float2 b0 = __half22float2(*(const __half2*)&braw.x);
    float2 b1 = __half22float2(*(const __half2*)&braw.y);
    float2 b2 = __half22float2(*(const __half2*)&braw.z);
    float2 b3 = __half22float2(*(const __half2*)&braw.w);
    float v[8] = {a0.x + b0.x, a0.y + b0.y, a0.z + b1.x, a0.w + b1.y,
                  a1.x + b2.x, a1.y + b2.y, a1.z + b3.x, a1.w + b3.y};
    float s = 0.f, s2 = 0.f;
    #pragma unroll
    for (int i = 0; i < 8; i++) { s += v[i]; s2 = fmaf(v[i], v[i], s2); }
    #pragma unroll
    for (int o = 16; o; o >>= 1) {
        s  += __shfl_xor_sync(0xffffffffu, s,  o);
        s2 += __shfl_xor_sync(0xffffffffu, s2, o);
    }
    float mu = s * (1.f / 256.f);
    float var = s2 * (1.f / 256.f) - mu * mu;
    float rstd = rsqrtf(var + 1e-5f);

    float4 gg0 = *(const float4*)(g + lane * 8);
    float4 gg1 = *(const float4*)(g + lane * 8 + 4);
    float4 bb0 = *(const float4*)(be + lane * 8);
    float4 bb1 = *(const float4*)(be + lane * 8 + 4);
    float gv[8] = {gg0.x, gg0.y, gg0.z, gg0.w, gg1.x, gg1.y, gg1.z, gg1.w};
    float bv[8] = {bb0.x, bb0.y, bb0.z, bb0.w, bb1.x, bb1.y, bb1.z, bb1.w};
    float o0[8];
    #pragma unroll
    for (int i = 0; i < 8; i++) o0[i] = (v[i] - mu) * rstd * gv[i] + bv[i];
    *(float4*)(out + base)     = make_float4(o0[0], o0[1], o0[2], o0[3]);
    *(float4*)(out + base + 4) = make_float4(o0[4], o0[5], o0[6], o0[7]);
    if (WRITEH) {
        __half2* oh = (__half2*)(outh + base);
        oh[0] = __floats2half2_rn(o0[0], o0[1]);
        oh[1] = __floats2half2_rn(o0[2], o0[3]);
        oh[2] = __floats2half2_rn(o0[4], o0[5]);
        oh[3] = __floats2half2_rn(o0[6], o0[7]);
    }
}

// ---------------- host launcher ----------------
extern "C" void kernel_launch(void* const* d_in, const int* in_sizes, int n_in,
                              void* d_out, int out_size)
{
    const float* src   = (const float*)d_in[0];
    const float* pos   = (const float*)d_in[1];
    const float* rp    = (const float*)d_in[2];
    const float* Wv    = (const float*)d_in[5];
    const float* bv    = (const float*)d_in[6];
    const float* Woff  = (const float*)d_in[7];
    const float* boff  = (const float*)d_in[8];
    const float* Wattn = (const float*)d_in[9];
    const float* battn = (const float*)d_in[10];
    const float* Wout  = (const float*)d_in[11];
    const float* bout  = (const float*)d_in[12];
    const float* W1    = (const float*)d_in[13];
    const float* b1    = (const float*)d_in[14];
    const float* W2    = (const float*)d_in[15];
    const float* b2    = (const float*)d_in[16];
    const float* g1    = (const float*)d_in[17];
    const float* be1   = (const float*)d_in[18];
    const float* g2    = (const float*)d_in[19];
    const float* be2   = (const float*)d_in[20];

    const int T = in_sizes[0] / DMODEL;   // N * Lq

    float  *p_x, *p_bpack;
    __half *p_x2h, *p_fh, *p_offattn_h, *p_value_h, *p_src_h, *p_q_h, *p_samp_h, *p_x_h, *p_h_h;
    __half *p_Wvt, *p_Wpackt, *p_Woutt, *p_W1t, *p_W2t;
    cudaGetSymbolAddress((void**)&p_x,       g_x);
    cudaGetSymbolAddress((void**)&p_x2h,     g_x2h);
    cudaGetSymbolAddress((void**)&p_fh,      g_fh);
    cudaGetSymbolAddress((void**)&p_bpack,   g_bpack);
    cudaGetSymbolAddress((void**)&p_offattn_h, g_offattn_h);
    cudaGetSymbolAddress((void**)&p_value_h, g_value_h);
    cudaGetSymbolAddress((void**)&p_src_h,   g_src_h);
    cudaGetSymbolAddress((void**)&p_q_h,     g_q_h);
    cudaGetSymbolAddress((void**)&p_samp_h,  g_samp_h);
    cudaGetSymbolAddress((void**)&p_x_h,     g_x_h);
    cudaGetSymbolAddress((void**)&p_h_h,     g_h_h);
    cudaGetSymbolAddress((void**)&p_Wvt,     g_Wvt);
    cudaGetSymbolAddress((void**)&p_Wpackt,  g_Wpackt);
    cudaGetSymbolAddress((void**)&p_Woutt,   g_Woutt);
    cudaGetSymbolAddress((void**)&p_W1t,     g_W1t);
    cudaGetSymbolAddress((void**)&p_W2t,     g_W2t);

    cudaFuncSetAttribute(hgemm_kernel<false, true>, cudaFuncAttributeMaxDynamicSharedMemorySize, GEMM_DSMEM);
    cudaFuncSetAttribute(hgemm_kernel<true,  true>, cudaFuncAttributeMaxDynamicSharedMemorySize, GEMM_DSMEM);
    cudaFuncSetAttribute(gemm12_kernel, cudaFuncAttributeMaxDynamicSharedMemorySize, GEMM_DSMEM);

    const int MB = (T + 127) / 128;
    const int n4 = T * DMODEL / 4;
    dim3 tb(32, 8);

    // ---- prep (2 launches) ----
    prep_w_kernel<<<738, tb>>>(Wv, Woff, Wout, Wattn, W1, W2, boff, battn);
    prep_act_kernel<<<(n4 + 255) / 256, 256>>>(src, pos, n4);

    // 1+2. value = src @ Wv + bv (half) ; offattn = q @ [W_off|W_attn] + b (half)
    gemm12_kernel<<<dim3(3, MB, 2), 256, GEMM_DSMEM>>>(
        p_src_h, p_Wvt, bv, p_value_h, p_q_h, p_Wpackt, p_bpack, p_offattn_h, T);

    // 3. deformable sampling + softmax fused (half out)
    sample_kernel<<<(T + 1) / 2, 128>>>(rp, T);

    // 4. x2 = samp @ W_out + b_out        (half out)
    hgemm_kernel<false, true><<<dim3(2, MB), 256, GEMM_DSMEM>>>(p_samp_h, p_Woutt, bout, p_x2h, T, 256, 256);

    // 5. x = LN(src + x2)                 (f32 + half)
    ln_kernel<true><<<(T * 32 + 255) / 256, 256>>>(src, p_x2h, g1, be1, p_x, p_x_h, T);

    // 6. h = relu(x @ W1 + b1)            (half out only)
    hgemm_kernel<true, true><<<dim3(8, MB), 256, GEMM_DSMEM>>>(p_x_h, p_W1t, b1, p_h_h, T, 1024, 256);

    // 7. f = h @ W2 + b2                  (half out)
    hgemm_kernel<false, true><<<dim3(2, MB), 256, GEMM_DSMEM>>>(p_h_h, p_W2t, b2, p_fh, T, 256, 1024);

    // 8. out = LN(x + f)
    ln_kernel<false><<<(T * 32 + 255) / 256, 256>>>(p_x, p_fh, g2, be2, (float*)d_out, nullptr, T);
}